// round 16
// baseline (speedup 1.0000x reference)
#include <cuda_runtime.h>
#include <cuda_bf16.h>
#include <mma.h>
#include <math.h>
#include <stdint.h>

using namespace nvcuda;

constexpr int BS  = 4;
constexpr int NV  = 4096;
constexpr int NP1 = 1024;
constexpr int NP2 = 256;

// ------------------------- scratch layout (single static buffer) ------------
constexpr size_t SC_F1     = 0;
constexpr size_t SC_FM1    = SC_F1     + sizeof(float) * BS * NV  * 256;
constexpr size_t SC_VP1    = SC_FM1    + sizeof(float) * BS * NV  * 128;
constexpr size_t SC_F2     = SC_VP1    + sizeof(float) * BS * NP1 * 3;
constexpr size_t SC_F3     = SC_F2     + sizeof(float) * BS * NP1 * 512;
constexpr size_t SC_FM3    = SC_F3     + sizeof(float) * BS * NP1 * 512;
constexpr size_t SC_VP2    = SC_FM3    + sizeof(float) * BS * NP1 * 256;
constexpr size_t SC_F4     = SC_VP2    + sizeof(float) * BS * NP2 * 3;
constexpr size_t SC_FM4    = SC_F4     + sizeof(float) * BS * NP2 * 1024;
constexpr size_t SC_FG     = SC_FM4    + sizeof(float) * BS * NP2 * 512;
constexpr size_t SC_PAHI   = SC_FG     + sizeof(float) * BS * 512;
constexpr size_t SC_PALO   = SC_PAHI   + sizeof(__nv_bfloat16) * BS * NV  * 256;
constexpr size_t SC_PBHI   = SC_PALO   + sizeof(__nv_bfloat16) * BS * NV  * 256;
constexpr size_t SC_PBLO   = SC_PBHI   + sizeof(__nv_bfloat16) * BS * NP1 * 512;
constexpr size_t SC_PCHI   = SC_PBLO   + sizeof(__nv_bfloat16) * BS * NP1 * 512;
constexpr size_t SC_PCLO   = SC_PCHI   + sizeof(__nv_bfloat16) * BS * NP2 * 512;
constexpr size_t SC_AH1    = SC_PCLO   + sizeof(__nv_bfloat16) * BS * NP2 * 512;
constexpr size_t SC_BH1    = SC_AH1    + sizeof(float) * BS * NV  * 512;
constexpr size_t SC_CH1    = SC_BH1    + sizeof(float) * BS * NP1 * 512;
constexpr size_t SC_DH1    = SC_CH1    + sizeof(float) * BS * NP2 * 512;
constexpr size_t SC_H1HI   = SC_DH1    + sizeof(float) * BS * 512;
constexpr size_t SC_H1LO   = SC_H1HI   + sizeof(__nv_bfloat16) * BS * NV * 512;
constexpr size_t SC_H2     = SC_H1LO   + sizeof(__nv_bfloat16) * BS * NV * 512;
constexpr size_t SC_CW1HI  = SC_H2     + sizeof(float) * BS * NV * 512;
constexpr size_t SC_CW1LO  = SC_CW1HI  + sizeof(__nv_bfloat16) * 512 * 1792;
constexpr size_t SC_CW2HI  = SC_CW1LO  + sizeof(__nv_bfloat16) * 512 * 1792;
constexpr size_t SC_CW2LO  = SC_CW2HI  + sizeof(__nv_bfloat16) * 512 * 512;
constexpr size_t SC_FMP1HI = SC_CW2LO  + sizeof(__nv_bfloat16) * 512 * 512;
constexpr size_t SC_FMP1LO = SC_FMP1HI + sizeof(__nv_bfloat16) * BS * NP1 * 128;
constexpr size_t SC_FMP2HI = SC_FMP1LO + sizeof(__nv_bfloat16) * BS * NP1 * 128;
constexpr size_t SC_FMP2LO = SC_FMP2HI + sizeof(__nv_bfloat16) * BS * NP2 * 256;
constexpr size_t SC_W1THI  = SC_FMP2LO + sizeof(__nv_bfloat16) * BS * NP2 * 256;
constexpr size_t SC_W1TLO  = SC_W1THI  + sizeof(__nv_bfloat16) * 256 * 128;
constexpr size_t SC_W2THI  = SC_W1TLO  + sizeof(__nv_bfloat16) * 256 * 128;
constexpr size_t SC_W2TLO  = SC_W2THI  + sizeof(__nv_bfloat16) * 512 * 128;
constexpr size_t SC_W3THI  = SC_W2TLO  + sizeof(__nv_bfloat16) * 512 * 128;
constexpr size_t SC_W3TLO  = SC_W3THI  + sizeof(__nv_bfloat16) * 512 * 256;
constexpr size_t SC_W4THI  = SC_W3TLO  + sizeof(__nv_bfloat16) * 512 * 256;
constexpr size_t SC_W4TLO  = SC_W4THI  + sizeof(__nv_bfloat16) * 1024 * 256;
constexpr size_t SC_NB1    = SC_W4TLO  + sizeof(__nv_bfloat16) * 1024 * 256;
constexpr size_t SC_NB2    = SC_NB1    + sizeof(int) * BS * NV  * 32;
constexpr size_t SC_NB3    = SC_NB2    + sizeof(int) * BS * NP1 * 32;
constexpr size_t SC_NEAR1  = SC_NB3    + sizeof(int) * BS * NP2 * 32;
constexpr size_t SC_NEAR2  = SC_NEAR1  + sizeof(int) * BS * NV;
constexpr size_t SC_TOTAL  = SC_NEAR2  + sizeof(int) * BS * NV;

__device__ __align__(256) unsigned char g_scratch[SC_TOTAL];

__device__ __forceinline__ void bf16_split(float v, __nv_bfloat16& h, __nv_bfloat16& l) {
    h = __float2bfloat16(v);
    l = __float2bfloat16(v - __bfloat162float(h));
}

__device__ __forceinline__ void cp_async16(void* sptr, const void* gptr) {
    uint32_t sa = (uint32_t)__cvta_generic_to_shared(sptr);
    asm volatile("cp.async.cg.shared.global [%0], [%1], 16;" :: "r"(sa), "l"(gptr));
}

// ------------------------- static stream/event context ----------------------
__global__ void noop_kernel() {}

struct StreamCtx {
    cudaStream_t s1, s2;
    cudaEvent_t evStart, evPrep, evPartA, evPartB, evS1Done;
    cudaEvent_t evPool1, evPool2, evF2, evF4, evFm4, evS2Done;
    StreamCtx() {
        cudaStreamCreateWithFlags(&s1, cudaStreamNonBlocking);
        cudaStreamCreateWithFlags(&s2, cudaStreamNonBlocking);
        cudaEventCreateWithFlags(&evStart,  cudaEventDisableTiming);
        cudaEventCreateWithFlags(&evPrep,   cudaEventDisableTiming);
        cudaEventCreateWithFlags(&evPartA,  cudaEventDisableTiming);
        cudaEventCreateWithFlags(&evPartB,  cudaEventDisableTiming);
        cudaEventCreateWithFlags(&evS1Done, cudaEventDisableTiming);
        cudaEventCreateWithFlags(&evPool1,  cudaEventDisableTiming);
        cudaEventCreateWithFlags(&evPool2,  cudaEventDisableTiming);
        cudaEventCreateWithFlags(&evF2,     cudaEventDisableTiming);
        cudaEventCreateWithFlags(&evF4,     cudaEventDisableTiming);
        cudaEventCreateWithFlags(&evFm4,    cudaEventDisableTiming);
        cudaEventCreateWithFlags(&evS2Done, cudaEventDisableTiming);
        noop_kernel<<<1, 1, 0, s1>>>();
        noop_kernel<<<1, 1, 0, s2>>>();
        cudaStreamSynchronize(s1);
        cudaStreamSynchronize(s2);
    }
};
static StreamCtx g_sc;

// ------------------------- tensor-core GEMM (wmma bf16, split precision) ----
constexpr int TC_SSTRIDE = 40;
constexpr int TC_TILE    = 128 * TC_SSTRIDE;
constexpr int TC_SMEM    = 2 * 4 * TC_TILE * 2;   // 81920 B

__global__ __launch_bounds__(256, 2) void tc_gemm_kernel(
    const __nv_bfloat16* __restrict__ Ahi, const __nv_bfloat16* __restrict__ Alo, int lda,
    const __nv_bfloat16* __restrict__ Bhi, const __nv_bfloat16* __restrict__ Blo, int ldb,
    float* __restrict__ C, int N, int K)
{
    extern __shared__ char smem[];
    __nv_bfloat16* sbuf = (__nv_bfloat16*)smem;

    const int tid  = threadIdx.x;
    const int warp = tid >> 5;
    const int wm   = warp >> 1;
    const int wn   = warp & 1;
    const int m0 = blockIdx.y * 128, n0 = blockIdx.x * 128;

    wmma::fragment<wmma::accumulator, 16, 16, 16, float> acc[2][4];
#pragma unroll
    for (int i = 0; i < 2; ++i)
#pragma unroll
        for (int j = 0; j < 4; ++j)
            wmma::fill_fragment(acc[i][j], 0.0f);

    const int nch = K / 32;

    auto load_stage = [&](int stage, int k0) {
        __nv_bfloat16* st = sbuf + stage * 4 * TC_TILE;
#pragma unroll
        for (int it = 0; it < 2; ++it) {
            const int i = tid + it * 256;
            const int row = i >> 2, c = (i & 3) * 8;
            const size_t gA = (size_t)(m0 + row) * lda + k0 + c;
            const size_t gB = (size_t)(n0 + row) * ldb + k0 + c;
            const int so = row * TC_SSTRIDE + c;
            cp_async16(st + 0 * TC_TILE + so, Ahi + gA);
            cp_async16(st + 1 * TC_TILE + so, Alo + gA);
            cp_async16(st + 2 * TC_TILE + so, Bhi + gB);
            cp_async16(st + 3 * TC_TILE + so, Blo + gB);
        }
        asm volatile("cp.async.commit_group;");
    };

    load_stage(0, 0);
    for (int ch = 0; ch < nch; ++ch) {
        if (ch + 1 < nch) {
            load_stage((ch + 1) & 1, (ch + 1) * 32);
            asm volatile("cp.async.wait_group 1;");
        } else {
            asm volatile("cp.async.wait_group 0;");
        }
        __syncthreads();
        const __nv_bfloat16* st = sbuf + (ch & 1) * 4 * TC_TILE;
        const __nv_bfloat16* sAhi = st + 0 * TC_TILE;
        const __nv_bfloat16* sAlo = st + 1 * TC_TILE;
        const __nv_bfloat16* sBhi = st + 2 * TC_TILE;
        const __nv_bfloat16* sBlo = st + 3 * TC_TILE;
#pragma unroll
        for (int ks = 0; ks < 32; ks += 16) {
            wmma::fragment<wmma::matrix_a, 16, 16, 16, __nv_bfloat16, wmma::row_major> ah[2], al[2];
#pragma unroll
            for (int i = 0; i < 2; ++i) {
                wmma::load_matrix_sync(ah[i], sAhi + (wm*32 + i*16) * TC_SSTRIDE + ks, TC_SSTRIDE);
                wmma::load_matrix_sync(al[i], sAlo + (wm*32 + i*16) * TC_SSTRIDE + ks, TC_SSTRIDE);
            }
#pragma unroll
            for (int j = 0; j < 4; ++j) {
                wmma::fragment<wmma::matrix_b, 16, 16, 16, __nv_bfloat16, wmma::col_major> bh, bl;
                wmma::load_matrix_sync(bh, sBhi + (wn*64 + j*16) * TC_SSTRIDE + ks, TC_SSTRIDE);
                wmma::load_matrix_sync(bl, sBlo + (wn*64 + j*16) * TC_SSTRIDE + ks, TC_SSTRIDE);
#pragma unroll
                for (int i = 0; i < 2; ++i) {
                    wmma::mma_sync(acc[i][j], ah[i], bh, acc[i][j]);
                    wmma::mma_sync(acc[i][j], ah[i], bl, acc[i][j]);
                    wmma::mma_sync(acc[i][j], al[i], bh, acc[i][j]);
                }
            }
        }
        __syncthreads();
    }

#pragma unroll
    for (int i = 0; i < 2; ++i)
#pragma unroll
        for (int j = 0; j < 4; ++j)
            wmma::store_matrix_sync(
                C + (size_t)(m0 + wm*32 + i*16) * N + n0 + wn*64 + j*16,
                acc[i][j], N, wmma::mem_row_major);
}

// ------------------------- merged weight prep --------------------------------
__global__ void prep_weights_kernel(
    const float* __restrict__ cw1, const float* __restrict__ cw2,
    const float* __restrict__ w1, const float* __restrict__ w2,
    const float* __restrict__ w3, const float* __restrict__ w4,
    __nv_bfloat16* __restrict__ cw1hi, __nv_bfloat16* __restrict__ cw1lo,
    __nv_bfloat16* __restrict__ cw2hi, __nv_bfloat16* __restrict__ cw2lo,
    __nv_bfloat16* __restrict__ w1thi, __nv_bfloat16* __restrict__ w1tlo,
    __nv_bfloat16* __restrict__ w2thi, __nv_bfloat16* __restrict__ w2tlo,
    __nv_bfloat16* __restrict__ w3thi, __nv_bfloat16* __restrict__ w3tlo,
    __nv_bfloat16* __restrict__ w4thi, __nv_bfloat16* __restrict__ w4tlo)
{
    int i = blockIdx.x * 256 + threadIdx.x;
    const int n0 = 512*1792, n1 = 512*512, n2 = 128*256,
              n3 = 128*512,  n4 = 256*512, n5 = 256*1024;
    __nv_bfloat16 h, l;
    if (i < n0) { bf16_split(cw1[i], h, l); cw1hi[i] = h; cw1lo[i] = l; return; }
    i -= n0;
    if (i < n1) { bf16_split(cw2[i], h, l); cw2hi[i] = h; cw2lo[i] = l; return; }
    i -= n1;
    if (i < n2) {
        int k = i / 256, n = i % 256;
        bf16_split(w1[i], h, l);
        w1thi[(size_t)n * 128 + k] = h; w1tlo[(size_t)n * 128 + k] = l; return;
    }
    i -= n2;
    if (i < n3) {
        int k = i / 512, n = i % 512;
        bf16_split(w2[i], h, l);
        w2thi[(size_t)n * 128 + k] = h; w2tlo[(size_t)n * 128 + k] = l; return;
    }
    i -= n3;
    if (i < n4) {
        int k = i / 512, n = i % 512;
        bf16_split(w3[i], h, l);
        w3thi[(size_t)n * 256 + k] = h; w3tlo[(size_t)n * 256 + k] = l; return;
    }
    i -= n4;
    if (i < n5) {
        int k = i / 1024, n = i % 1024;
        bf16_split(w4[i], h, l);
        w4thi[(size_t)n * 256 + k] = h; w4tlo[(size_t)n * 256 + k] = l;
    }
}
constexpr int PREP_TOTAL = 512*1792 + 512*512 + 128*256 + 128*512 + 256*512 + 256*1024;

// ------------------------- warp-cooperative KNN-32 (multi-pass cache) -------
// float4 cache {x,y,z,|p|^2}; d = |p|^2 - 2 p.q. Candidates processed in
// P/PH passes of PH points each (smaller smem -> higher occupancy).
__device__ __forceinline__ void knn_cmpex(float& d, int& i, int lane, int s, bool up) {
    const float od = __shfl_xor_sync(0xffffffffu, d, s);
    const int   oi = __shfl_xor_sync(0xffffffffu, i, s);
    const bool lower = (lane & s) == 0;
    if ((od != d) && ((d > od) == (lower == up))) { d = od; i = oi; }
}

__global__ __launch_bounds__(512) void knn32_warp_kernel(
    const float* __restrict__ pts, int P, int PH, int* __restrict__ out)
{
    extern __shared__ float4 sp4[];
    const int b = blockIdx.y;
    const float* vb = pts + (size_t)b * P * 3;
    const int lane = threadIdx.x & 31;
    const int q = blockIdx.x * 16 + (threadIdx.x >> 5);
    const float qx = vb[3*q], qy = vb[3*q+1], qz = vb[3*q+2];
    float Ld = 3.0e38f; int Li = 0;
    for (int base = 0; base < P; base += PH) {
        __syncthreads();                   // protect smem reuse across passes
        for (int i = threadIdx.x; i < PH; i += 512) {
            const int g = base + i;
            const float x = vb[3*g], y = vb[3*g+1], z = vb[3*g+2];
            sp4[i] = make_float4(x, y, z, fmaf(x, x, fmaf(y, y, z * z)));
        }
        __syncthreads();
        const bool qin = (q >= base) && (q < base + PH);
        const int qb = (q - base) & ~31;
        for (int j0 = 0; j0 < PH; j0 += 32) {
            const float4 p = sp4[j0 + lane];
            float t = fmaf(p.x, qx, fmaf(p.y, qy, p.z * qz));
            float d = fmaf(-2.0f, t, p.w);
            if (qin && j0 == qb) {         // uniform branch; self is global min
                if (base + j0 + lane == q) d = 3.0e38f;
            }
            const float worst = __shfl_sync(0xffffffffu, Ld, 31);
            unsigned mask = __ballot_sync(0xffffffffu, d < worst);
            if (!mask) continue;
            if (__popc(mask) <= 8) {
                while (mask) {
                    const int src = __ffs(mask) - 1;
                    mask &= mask - 1;
                    const float cd = __shfl_sync(0xffffffffu, d, src);
                    const int   ci = base + j0 + src;
                    const int pos = __popc(__ballot_sync(0xffffffffu, Ld < cd));
                    const float pd = __shfl_up_sync(0xffffffffu, Ld, 1);
                    const int   pi = __shfl_up_sync(0xffffffffu, Li, 1);
                    if (lane > pos)       { Ld = pd; Li = pi; }
                    else if (lane == pos) { Ld = cd; Li = ci; }
                }
            } else {
                float cd = d; int ci = base + j0 + lane;
#pragma unroll
                for (int k = 2; k <= 32; k <<= 1) {
                    const bool up = ((lane & k) == 0);
#pragma unroll
                    for (int s2 = k >> 1; s2 > 0; s2 >>= 1) knn_cmpex(cd, ci, lane, s2, up);
                }
                const float rd = __shfl_sync(0xffffffffu, cd, 31 - lane);
                const int   ri = __shfl_sync(0xffffffffu, ci, 31 - lane);
                if (rd < Ld) { Ld = rd; Li = ri; }
#pragma unroll
                for (int s2 = 16; s2 > 0; s2 >>= 1) knn_cmpex(Ld, Li, lane, s2, true);
            }
        }
    }
    out[((size_t)b * P + q) * 32 + lane] = Li;
}

// ------------------------- nearest (argmin; float4 trick) --------------------
__global__ void nearest_kernel(const float* __restrict__ qpts, int Q,
                               const float* __restrict__ spts, int P,
                               int* __restrict__ out)
{
    extern __shared__ float4 sp4[];
    const int b = blockIdx.y;
    const float* sb = spts + (size_t)b * P * 3;
    for (int i = threadIdx.x; i < P; i += blockDim.x) {
        const float x = sb[3*i], y = sb[3*i+1], z = sb[3*i+2];
        sp4[i] = make_float4(x, y, z, fmaf(x, x, fmaf(y, y, z * z)));
    }
    __syncthreads();
    const int q = blockIdx.x * blockDim.x + threadIdx.x;
    if (q >= Q) return;
    const float* qb = qpts + ((size_t)b * Q + q) * 3;
    const float qx = qb[0], qy = qb[1], qz = qb[2];
    float best = 3.0e38f; int bi = 0;
#pragma unroll 4
    for (int j = 0; j < P; ++j) {
        const float4 p = sp4[j];
        float t = fmaf(p.x, qx, fmaf(p.y, qy, p.z * qz));
        float d = fmaf(-2.0f, t, p.w);
        if (d < best) { best = d; bi = j; }
    }
    out[(size_t)b * Q + q] = bi;
}

// ------------------------- conv_surface (vec4: 32 threads, 4 ch each) -------
__global__ void conv_surface_kernel(const float* __restrict__ verts,
                                    const int* __restrict__ nb,
                                    const float* __restrict__ dirs,
                                    __nv_bfloat16* __restrict__ ohi,
                                    __nv_bfloat16* __restrict__ olo)
{
    __shared__ float ux[32], uy[32], uz[32];
    const int bv = blockIdx.x;
    const int b = bv >> 12;
    const float* vb = verts + (size_t)b * NV * 3;
    const int v = bv & 4095;
    const int t = threadIdx.x;
    {
        const float cx = vb[3*v], cy = vb[3*v+1], cz = vb[3*v+2];
        int j = nb[(size_t)bv * 32 + t];
        float dx = vb[3*j]-cx, dy = vb[3*j+1]-cy, dz = vb[3*j+2]-cz;
        float n = fmaxf(sqrtf(dx*dx + dy*dy + dz*dz), 1e-12f);
        ux[t] = dx/n; uy[t] = dy/n; uz[t] = dz/n;
    }
    __syncthreads();
    const int c = t * 4;
    float4 D0 = *(const float4*)(dirs + c);
    float4 D1 = *(const float4*)(dirs + 128 + c);
    float4 D2 = *(const float4*)(dirs + 256 + c);
    float d0[4] = {D0.x, D0.y, D0.z, D0.w};
    float d1[4] = {D1.x, D1.y, D1.z, D1.w};
    float d2[4] = {D2.x, D2.y, D2.z, D2.w};
#pragma unroll
    for (int j = 0; j < 4; ++j) {
        float n = fmaxf(sqrtf(d0[j]*d0[j] + d1[j]*d1[j] + d2[j]*d2[j]), 1e-12f);
        d0[j] /= n; d1[j] /= n; d2[j] /= n;
    }
    float acc[4] = {0.f, 0.f, 0.f, 0.f};
#pragma unroll 4
    for (int k = 0; k < 32; ++k) {
        const float u0 = ux[k], u1 = uy[k], u2 = uz[k];
#pragma unroll
        for (int j = 0; j < 4; ++j)
            acc[j] = fmaxf(acc[j], fmaf(u0, d0[j], fmaf(u1, d1[j], u2 * d2[j])));
    }
#pragma unroll
    for (int j = 0; j < 4; ++j) {
        __nv_bfloat16 h, l; bf16_split(acc[j], h, l);
        ohi[(size_t)bv * 256 + c + j] = h;
        olo[(size_t)bv * 256 + c + j] = l;
    }
}

// ------------------------- conv_layer combine (vec4; bias folded in) --------
__global__ void conv_combine_kernel(const float* __restrict__ verts,
                                    const int* __restrict__ nb,
                                    const float* __restrict__ f,
                                    const float* __restrict__ bias,
                                    const float* __restrict__ dirs,
                                    float* __restrict__ out,
                                    __nv_bfloat16* __restrict__ ohi,
                                    __nv_bfloat16* __restrict__ olo,
                                    int ostride,
                                    int P, int C, int doRelu)
{
    __shared__ float ux[32], uy[32], uz[32];
    __shared__ int snb[32];
    const int bv = blockIdx.x;
    const int b = bv / P, v = bv % P;
    const float* vb = verts + (size_t)b * P * 3;
    const int t = threadIdx.x;
    if (t < 32) {
        const float cx = vb[3*v], cy = vb[3*v+1], cz = vb[3*v+2];
        int j = nb[(size_t)bv * 32 + t];
        snb[t] = j;
        float dx = vb[3*j]-cx, dy = vb[3*j+1]-cy, dz = vb[3*j+2]-cz;
        float n = fmaxf(sqrtf(dx*dx + dy*dy + dz*dz), 1e-12f);
        ux[t] = dx/n; uy[t] = dy/n; uz[t] = dz/n;
    }
    __syncthreads();
    const int c = t * 4;
    float4 D0 = *(const float4*)(dirs + c);
    float4 D1 = *(const float4*)(dirs + C + c);
    float4 D2 = *(const float4*)(dirs + 2*C + c);
    float d0[4] = {D0.x, D0.y, D0.z, D0.w};
    float d1[4] = {D1.x, D1.y, D1.z, D1.w};
    float d2[4] = {D2.x, D2.y, D2.z, D2.w};
#pragma unroll
    for (int j = 0; j < 4; ++j) {
        float n = fmaxf(sqrtf(d0[j]*d0[j] + d1[j]*d1[j] + d2[j]*d2[j]), 1e-12f);
        d0[j] /= n; d1[j] /= n; d2[j] /= n;
    }
    const float4 bc = *(const float4*)(bias + c);
    const float4 bs = *(const float4*)(bias + C + c);
    const float* fb   = f + (size_t)b * P * 2 * C;
    const float* fsup = fb + C + c;
    float m[4] = {-3.0e38f, -3.0e38f, -3.0e38f, -3.0e38f};
#pragma unroll 4
    for (int k = 0; k < 32; ++k) {
        const float u0 = ux[k], u1 = uy[k], u2 = uz[k];
        const float4 sup = *(const float4*)(fsup + (size_t)snb[k] * 2 * C);
        float th0 = fmaxf(0.0f, fmaf(u0, d0[0], fmaf(u1, d1[0], u2 * d2[0])));
        float th1 = fmaxf(0.0f, fmaf(u0, d0[1], fmaf(u1, d1[1], u2 * d2[1])));
        float th2 = fmaxf(0.0f, fmaf(u0, d0[2], fmaf(u1, d1[2], u2 * d2[2])));
        float th3 = fmaxf(0.0f, fmaf(u0, d0[3], fmaf(u1, d1[3], u2 * d2[3])));
        m[0] = fmaxf(m[0], th0 * (sup.x + bs.x));
        m[1] = fmaxf(m[1], th1 * (sup.y + bs.y));
        m[2] = fmaxf(m[2], th2 * (sup.z + bs.z));
        m[3] = fmaxf(m[3], th3 * (sup.w + bs.w));
    }
    const float4 ctr = *(const float4*)(fb + (size_t)v * 2 * C + c);
    float r[4] = {ctr.x + bc.x + m[0], ctr.y + bc.y + m[1],
                  ctr.z + bc.z + m[2], ctr.w + bc.w + m[3]};
    if (doRelu) {
#pragma unroll
        for (int j = 0; j < 4; ++j) r[j] = fmaxf(r[j], 0.0f);
    }
    if (out) {
        float4 o4 = {r[0], r[1], r[2], r[3]};
        *(float4*)(out + (size_t)bv * C + c) = o4;
    }
    if (ohi) {
#pragma unroll
        for (int j = 0; j < 4; ++j) {
            __nv_bfloat16 h, l; bf16_split(r[j], h, l);
            ohi[(size_t)bv * ostride + c + j] = h;
            olo[(size_t)bv * ostride + c + j] = l;
        }
    }
}

// ------------------------- pool: first-4 of sorted 32-NN --------------------
__global__ void pool_kernel(const float* __restrict__ verts,
                            const float* __restrict__ fm, int P, int C,
                            const int* __restrict__ sidx,
                            const int* __restrict__ nb32, int Q,
                            float* __restrict__ vout,
                            __nv_bfloat16* __restrict__ fhi,
                            __nv_bfloat16* __restrict__ flo)
{
    const int bq = blockIdx.x;
    const int b = bq / Q, q = bq % Q;
    const int k = threadIdx.x;
    const int qi = sidx[q];
    const int* nbq = nb32 + ((size_t)b * P + qi) * 32;
    const float* fb = fm + (size_t)b * P * C;
    float m = -3.0e38f;
#pragma unroll
    for (int s = 0; s < 4; ++s)
        m = fmaxf(m, fb[(size_t)nbq[s] * C + k]);
    __nv_bfloat16 h, l; bf16_split(m, h, l);
    fhi[(size_t)bq * C + k] = h;
    flo[(size_t)bq * C + k] = l;
    if (k < 3) {
        vout[(size_t)bq * 3 + k] = verts[((size_t)b * P + qi) * 3 + k];
    }
}

// ------------------------- global max over verts ----------------------------
__global__ void fglobal_kernel(const float* __restrict__ fm4,
                               float* __restrict__ fg)
{
    const int b = blockIdx.x, k = threadIdx.x;
    float m = -3.0e38f;
    for (int q = 0; q < NP2; ++q)
        m = fmaxf(m, fm4[((size_t)b * NP2 + q) * 512 + k]);
    fg[(size_t)b * 512 + k] = m;
}

// ------------------------- Dh1 = fg @ cw1[:,1280:1792]^T (fp32, tiny) -------
__global__ void fg_head_kernel(const float* __restrict__ fg,
                               const float* __restrict__ cw1,
                               float* __restrict__ dh1)
{
    const int warp = threadIdx.x >> 5, lane = threadIdx.x & 31;
    const int o = blockIdx.x * 8 + warp;
    const int b = blockIdx.y;
    const float* fgb = fg + (size_t)b * 512;
    const float* wr  = cw1 + (size_t)o * 1792 + 1280;
    float acc = 0.0f;
#pragma unroll
    for (int i = lane; i < 512; i += 32) acc = fmaf(fgb[i], wr[i], acc);
#pragma unroll
    for (int s = 16; s > 0; s >>= 1)
        acc += __shfl_down_sync(0xffffffffu, acc, s);
    if (lane == 0) dh1[(size_t)b * 512 + o] = acc;
}

// ------------------------- h1 combine: gather-add parts + cb1 + relu --------
__global__ void h1_combine_kernel(const float* __restrict__ Ah1,
                                  const float* __restrict__ Bh1,
                                  const float* __restrict__ Ch1,
                                  const float* __restrict__ Dh1,
                                  const float* __restrict__ cb1,
                                  const int* __restrict__ near1,
                                  const int* __restrict__ near2,
                                  __nv_bfloat16* __restrict__ h1hi,
                                  __nv_bfloat16* __restrict__ h1lo)
{
    const int bv = blockIdx.x;
    const int b = bv >> 12;
    const int n1 = near1[bv], n2 = near2[bv];
    const int o = threadIdx.x;
    float v = Ah1[(size_t)bv * 512 + o]
            + Bh1[((size_t)b * NP1 + n1) * 512 + o]
            + Ch1[((size_t)b * NP2 + n2) * 512 + o]
            + Dh1[(size_t)b * 512 + o]
            + cb1[o];
    v = fmaxf(v, 0.0f);
    __nv_bfloat16 h, l; bf16_split(v, h, l);
    h1hi[(size_t)bv * 512 + o] = h;
    h1lo[(size_t)bv * 512 + o] = l;
}

// ------------------------- final 13-way head (folds relu(h2+cb2)) -----------
__global__ void head13_kernel(const float* __restrict__ h,
                              const float* __restrict__ hbias,
                              const float* __restrict__ w,
                              const float* __restrict__ bias,
                              float* __restrict__ out)
{
    const int warp = threadIdx.x >> 5, lane = threadIdx.x & 31;
    const float* hr = h + (size_t)blockIdx.x * 512;
    const float* wr = w + (size_t)warp * 512;
    float acc = 0.0f;
#pragma unroll
    for (int i = lane; i < 512; i += 32) {
        float hv = fmaxf(hr[i] + hbias[i], 0.0f);
        acc = fmaf(hv, wr[i], acc);
    }
#pragma unroll
    for (int o = 16; o > 0; o >>= 1)
        acc += __shfl_down_sync(0xffffffffu, acc, o);
    if (lane == 0) out[(size_t)blockIdx.x * 13 + warp] = acc + bias[warp];
}

// ------------------------- launcher ------------------------------------------
extern "C" void kernel_launch(void* const* d_in, const int* in_sizes, int n_in,
                              void* d_out, int out_size)
{
    const float* verts = (const float*)d_in[0];
    const int*   sidx1 = (const int*)  d_in[1];
    const int*   sidx2 = (const int*)  d_in[2];
    const float* dir0  = (const float*)d_in[3];
    const float* w1 = (const float*)d_in[4];
    const float* b1 = (const float*)d_in[5];
    const float* d1 = (const float*)d_in[6];
    const float* w2 = (const float*)d_in[7];
    const float* b2 = (const float*)d_in[8];
    const float* d2 = (const float*)d_in[9];
    const float* w3 = (const float*)d_in[10];
    const float* b3 = (const float*)d_in[11];
    const float* d3 = (const float*)d_in[12];
    const float* w4 = (const float*)d_in[13];
    const float* b4 = (const float*)d_in[14];
    const float* d4 = (const float*)d_in[15];
    const float* cw1 = (const float*)d_in[16];
    const float* cb1 = (const float*)d_in[17];
    const float* cw2 = (const float*)d_in[18];
    const float* cb2 = (const float*)d_in[19];
    const float* cw3 = (const float*)d_in[20];
    const float* cb3 = (const float*)d_in[21];

    void* sp = nullptr;
    cudaGetSymbolAddress(&sp, g_scratch);
    char* s = (char*)sp;
    float* f1   = (float*)(s + SC_F1);
    float* fm1  = (float*)(s + SC_FM1);
    float* vp1  = (float*)(s + SC_VP1);
    float* f2   = (float*)(s + SC_F2);
    float* f3   = (float*)(s + SC_F3);
    float* fm3  = (float*)(s + SC_FM3);
    float* vp2  = (float*)(s + SC_VP2);
    float* f4   = (float*)(s + SC_F4);
    float* fm4  = (float*)(s + SC_FM4);
    float* fg   = (float*)(s + SC_FG);
    __nv_bfloat16* pahi = (__nv_bfloat16*)(s + SC_PAHI);
    __nv_bfloat16* palo = (__nv_bfloat16*)(s + SC_PALO);
    __nv_bfloat16* pbhi = (__nv_bfloat16*)(s + SC_PBHI);
    __nv_bfloat16* pblo = (__nv_bfloat16*)(s + SC_PBLO);
    __nv_bfloat16* pchi = (__nv_bfloat16*)(s + SC_PCHI);
    __nv_bfloat16* pclo = (__nv_bfloat16*)(s + SC_PCLO);
    float* Ah1 = (float*)(s + SC_AH1);
    float* Bh1 = (float*)(s + SC_BH1);
    float* Ch1 = (float*)(s + SC_CH1);
    float* Dh1 = (float*)(s + SC_DH1);
    __nv_bfloat16* h1hi = (__nv_bfloat16*)(s + SC_H1HI);
    __nv_bfloat16* h1lo = (__nv_bfloat16*)(s + SC_H1LO);
    float* h2   = (float*)(s + SC_H2);
    __nv_bfloat16* cw1hi = (__nv_bfloat16*)(s + SC_CW1HI);
    __nv_bfloat16* cw1lo = (__nv_bfloat16*)(s + SC_CW1LO);
    __nv_bfloat16* cw2hi = (__nv_bfloat16*)(s + SC_CW2HI);
    __nv_bfloat16* cw2lo = (__nv_bfloat16*)(s + SC_CW2LO);
    __nv_bfloat16* fmp1hi = (__nv_bfloat16*)(s + SC_FMP1HI);
    __nv_bfloat16* fmp1lo = (__nv_bfloat16*)(s + SC_FMP1LO);
    __nv_bfloat16* fmp2hi = (__nv_bfloat16*)(s + SC_FMP2HI);
    __nv_bfloat16* fmp2lo = (__nv_bfloat16*)(s + SC_FMP2LO);
    __nv_bfloat16* w1thi = (__nv_bfloat16*)(s + SC_W1THI);
    __nv_bfloat16* w1tlo = (__nv_bfloat16*)(s + SC_W1TLO);
    __nv_bfloat16* w2thi = (__nv_bfloat16*)(s + SC_W2THI);
    __nv_bfloat16* w2tlo = (__nv_bfloat16*)(s + SC_W2TLO);
    __nv_bfloat16* w3thi = (__nv_bfloat16*)(s + SC_W3THI);
    __nv_bfloat16* w3tlo = (__nv_bfloat16*)(s + SC_W3TLO);
    __nv_bfloat16* w4thi = (__nv_bfloat16*)(s + SC_W4THI);
    __nv_bfloat16* w4tlo = (__nv_bfloat16*)(s + SC_W4TLO);
    int* nb1   = (int*)(s + SC_NB1);
    int* nb2   = (int*)(s + SC_NB2);
    int* nb3   = (int*)(s + SC_NB3);
    int* near1 = (int*)(s + SC_NEAR1);
    int* near2 = (int*)(s + SC_NEAR2);

    cudaFuncSetAttribute(tc_gemm_kernel,
                         cudaFuncAttributeMaxDynamicSharedMemorySize, TC_SMEM);
    cudaFuncSetAttribute(knn32_warp_kernel,
                         cudaFuncAttributeMaxDynamicSharedMemorySize, NV * 8);
    cudaFuncSetAttribute(nearest_kernel,
                         cudaFuncAttributeMaxDynamicSharedMemorySize, NP1 * 16);

    // ---- fork: weight prep on s2 overlaps knn1 on main -------------------
    cudaEventRecord(g_sc.evStart, 0);
    cudaStreamWaitEvent(g_sc.s2, g_sc.evStart, 0);
    prep_weights_kernel<<<(PREP_TOTAL + 255)/256, 256, 0, g_sc.s2>>>(
        cw1, cw2, w1, w2, w3, w4,
        cw1hi, cw1lo, cw2hi, cw2lo,
        w1thi, w1tlo, w2thi, w2tlo, w3thi, w3tlo, w4thi, w4tlo);
    cudaEventRecord(g_sc.evPrep, g_sc.s2);

    // Level 0/1 on full 4096-point cloud (main). knn1: 2 passes of 2048.
    knn32_warp_kernel<<<dim3(NV/16, BS), 512, (NV/2) * 16>>>(verts, NV, NV/2, nb1);
    conv_surface_kernel<<<BS*NV, 32>>>(verts, nb1, dir0, pahi, palo);
    cudaStreamWaitEvent(0, g_sc.evPrep, 0);
    tc_gemm_kernel<<<dim3(2, 128), 256, TC_SMEM>>>(
        pahi, palo, 256, w1thi, w1tlo, 128, f1, 256, 128);
    conv_combine_kernel<<<BS*NV, 32>>>(verts, nb1, f1, b1, d1, fm1,
        pahi + 128, palo + 128, 256, NV, 128, 1);
    cudaEventRecord(g_sc.evPartA, 0);

    // ---- fork: Ah1 on s1 overlaps the level-2/3 chain --------------------
    cudaStreamWaitEvent(g_sc.s1, g_sc.evPartA, 0);
    tc_gemm_kernel<<<dim3(4, 128), 256, TC_SMEM, g_sc.s1>>>(
        pahi, palo, 256, cw1hi, cw1lo, 1792, Ah1, 512, 256);

    // Pool 1 (main); nearest1 + f2 on s2 overlap knn2 on main
    pool_kernel<<<BS*NP1, 128>>>(verts, fm1, NV, 128, sidx1, nb1, NP1, vp1, fmp1hi, fmp1lo);
    cudaEventRecord(g_sc.evPool1, 0);
    cudaStreamWaitEvent(g_sc.s2, g_sc.evPool1, 0);
    nearest_kernel<<<dim3(NV/256, BS), 256, NP1 * 16, g_sc.s2>>>(
        verts, NV, vp1, NP1, near1);
    tc_gemm_kernel<<<dim3(4, 32), 256, TC_SMEM, g_sc.s2>>>(
        fmp1hi, fmp1lo, 128, w2thi, w2tlo, 128, f2, 512, 128);
    cudaEventRecord(g_sc.evF2, g_sc.s2);

    knn32_warp_kernel<<<dim3(NP1/16, BS), 512, NP1 * 16>>>(vp1, NP1, NP1, nb2);

    cudaStreamWaitEvent(0, g_sc.evF2, 0);
    conv_combine_kernel<<<BS*NP1, 64>>>(vp1, nb2, f2, b2, d2, nullptr,
        pbhi, pblo, 512, NP1, 256, 1);
    tc_gemm_kernel<<<dim3(4, 32), 256, TC_SMEM>>>(
        pbhi, pblo, 512, w3thi, w3tlo, 256, f3, 512, 256);
    conv_combine_kernel<<<BS*NP1, 64>>>(vp1, nb2, f3, b3, d3, fm3,
        pbhi + 256, pblo + 256, 512, NP1, 256, 1);
    cudaEventRecord(g_sc.evPartB, 0);

    // ---- s1: Bh1 after partB, overlaps the level-4 chain -----------------
    cudaStreamWaitEvent(g_sc.s1, g_sc.evPartB, 0);
    tc_gemm_kernel<<<dim3(4, 32), 256, TC_SMEM, g_sc.s1>>>(
        pbhi, pblo, 512, cw1hi + 256, cw1lo + 256, 1792, Bh1, 512, 512);
    cudaEventRecord(g_sc.evS1Done, g_sc.s1);

    // Pool 2 (main); nearest2 + f4 on s2 overlap knn3 on main
    pool_kernel<<<BS*NP2, 256>>>(vp1, fm3, NP1, 256, sidx2, nb2, NP2, vp2, fmp2hi, fmp2lo);
    cudaEventRecord(g_sc.evPool2, 0);
    cudaStreamWaitEvent(g_sc.s2, g_sc.evPool2, 0);
    nearest_kernel<<<dim3(NV/256, BS), 256, NP2 * 16, g_sc.s2>>>(
        verts, NV, vp2, NP2, near2);
    tc_gemm_kernel<<<dim3(8, 8), 256, TC_SMEM, g_sc.s2>>>(
        fmp2hi, fmp2lo, 256, w4thi, w4tlo, 256, f4, 1024, 256);
    cudaEventRecord(g_sc.evF4, g_sc.s2);

    knn32_warp_kernel<<<dim3(NP2/16, BS), 512, NP2 * 16>>>(vp2, NP2, NP2, nb3);

    cudaStreamWaitEvent(0, g_sc.evF4, 0);
    conv_combine_kernel<<<BS*NP2, 128>>>(vp2, nb3, f4, b4, d4, fm4,
        pchi, pclo, 512, NP2, 512, 0);
    cudaEventRecord(g_sc.evFm4, 0);

    // fglobal + fg_head on s2 overlap Ch1 GEMM on main
    cudaStreamWaitEvent(g_sc.s2, g_sc.evFm4, 0);
    fglobal_kernel<<<BS, 512, 0, g_sc.s2>>>(fm4, fg);
    fg_head_kernel<<<dim3(64, BS), 256, 0, g_sc.s2>>>(fg, cw1, Dh1);
    cudaEventRecord(g_sc.evS2Done, g_sc.s2);

    tc_gemm_kernel<<<dim3(4, 8), 256, TC_SMEM>>>(
        pchi, pclo, 512, cw1hi + 768, cw1lo + 768, 1792, Ch1, 512, 512);

    // ---- join all, then combine + h2 + head ------------------------------
    cudaStreamWaitEvent(0, g_sc.evS1Done, 0);
    cudaStreamWaitEvent(0, g_sc.evS2Done, 0);
    h1_combine_kernel<<<BS*NV, 512>>>(Ah1, Bh1, Ch1, Dh1, cb1, near1, near2, h1hi, h1lo);
    tc_gemm_kernel<<<dim3(512/128, (BS*NV)/128), 256, TC_SMEM>>>(
        h1hi, h1lo, 512, cw2hi, cw2lo, 512, h2, 512, 512);
    head13_kernel<<<BS*NV, 13*32>>>(h2, cb2, cw3, cb3, (float*)d_out);
}

// round 17
// speedup vs baseline: 1.0327x; 1.0327x over previous
#include <cuda_runtime.h>
#include <cuda_bf16.h>
#include <mma.h>
#include <math.h>
#include <stdint.h>

using namespace nvcuda;

constexpr int BS  = 4;
constexpr int NV  = 4096;
constexpr int NP1 = 1024;
constexpr int NP2 = 256;

// ------------------------- scratch layout (single static buffer) ------------
constexpr size_t SC_F1     = 0;
constexpr size_t SC_FM1    = SC_F1     + sizeof(float) * BS * NV  * 256;
constexpr size_t SC_VP1    = SC_FM1    + sizeof(float) * BS * NV  * 128;
constexpr size_t SC_F2     = SC_VP1    + sizeof(float) * BS * NP1 * 3;
constexpr size_t SC_F3     = SC_F2     + sizeof(float) * BS * NP1 * 512;
constexpr size_t SC_FM3    = SC_F3     + sizeof(float) * BS * NP1 * 512;
constexpr size_t SC_VP2    = SC_FM3    + sizeof(float) * BS * NP1 * 256;
constexpr size_t SC_F4     = SC_VP2    + sizeof(float) * BS * NP2 * 3;
constexpr size_t SC_FM4    = SC_F4     + sizeof(float) * BS * NP2 * 1024;
constexpr size_t SC_FG     = SC_FM4    + sizeof(float) * BS * NP2 * 512;
constexpr size_t SC_PAHI   = SC_FG     + sizeof(float) * BS * 512;
constexpr size_t SC_PALO   = SC_PAHI   + sizeof(__nv_bfloat16) * BS * NV  * 256;
constexpr size_t SC_PBHI   = SC_PALO   + sizeof(__nv_bfloat16) * BS * NV  * 256;
constexpr size_t SC_PBLO   = SC_PBHI   + sizeof(__nv_bfloat16) * BS * NP1 * 512;
constexpr size_t SC_PCHI   = SC_PBLO   + sizeof(__nv_bfloat16) * BS * NP1 * 512;
constexpr size_t SC_PCLO   = SC_PCHI   + sizeof(__nv_bfloat16) * BS * NP2 * 512;
constexpr size_t SC_AH1    = SC_PCLO   + sizeof(__nv_bfloat16) * BS * NP2 * 512;
constexpr size_t SC_BH1    = SC_AH1    + sizeof(float) * BS * NV  * 512;
constexpr size_t SC_CH1    = SC_BH1    + sizeof(float) * BS * NP1 * 512;
constexpr size_t SC_DH1    = SC_CH1    + sizeof(float) * BS * NP2 * 512;
constexpr size_t SC_H1HI   = SC_DH1    + sizeof(float) * BS * 512;
constexpr size_t SC_H1LO   = SC_H1HI   + sizeof(__nv_bfloat16) * BS * NV * 512;
constexpr size_t SC_H2     = SC_H1LO   + sizeof(__nv_bfloat16) * BS * NV * 512;
constexpr size_t SC_CW1HI  = SC_H2     + sizeof(float) * BS * NV * 512;
constexpr size_t SC_CW1LO  = SC_CW1HI  + sizeof(__nv_bfloat16) * 512 * 1792;
constexpr size_t SC_CW2HI  = SC_CW1LO  + sizeof(__nv_bfloat16) * 512 * 1792;
constexpr size_t SC_CW2LO  = SC_CW2HI  + sizeof(__nv_bfloat16) * 512 * 512;
constexpr size_t SC_FMP1HI = SC_CW2LO  + sizeof(__nv_bfloat16) * 512 * 512;
constexpr size_t SC_FMP1LO = SC_FMP1HI + sizeof(__nv_bfloat16) * BS * NP1 * 128;
constexpr size_t SC_FMP2HI = SC_FMP1LO + sizeof(__nv_bfloat16) * BS * NP1 * 128;
constexpr size_t SC_FMP2LO = SC_FMP2HI + sizeof(__nv_bfloat16) * BS * NP2 * 256;
constexpr size_t SC_W1THI  = SC_FMP2LO + sizeof(__nv_bfloat16) * BS * NP2 * 256;
constexpr size_t SC_W1TLO  = SC_W1THI  + sizeof(__nv_bfloat16) * 256 * 128;
constexpr size_t SC_W2THI  = SC_W1TLO  + sizeof(__nv_bfloat16) * 256 * 128;
constexpr size_t SC_W2TLO  = SC_W2THI  + sizeof(__nv_bfloat16) * 512 * 128;
constexpr size_t SC_W3THI  = SC_W2TLO  + sizeof(__nv_bfloat16) * 512 * 128;
constexpr size_t SC_W3TLO  = SC_W3THI  + sizeof(__nv_bfloat16) * 512 * 256;
constexpr size_t SC_W4THI  = SC_W3TLO  + sizeof(__nv_bfloat16) * 512 * 256;
constexpr size_t SC_W4TLO  = SC_W4THI  + sizeof(__nv_bfloat16) * 1024 * 256;
constexpr size_t SC_NB1    = SC_W4TLO  + sizeof(__nv_bfloat16) * 1024 * 256;
constexpr size_t SC_NB2    = SC_NB1    + sizeof(int) * BS * NV  * 32;
constexpr size_t SC_NB3    = SC_NB2    + sizeof(int) * BS * NP1 * 32;
constexpr size_t SC_NEAR1  = SC_NB3    + sizeof(int) * BS * NP2 * 32;
constexpr size_t SC_NEAR2  = SC_NEAR1  + sizeof(int) * BS * NV;
constexpr size_t SC_TOTAL  = SC_NEAR2  + sizeof(int) * BS * NV;

__device__ __align__(256) unsigned char g_scratch[SC_TOTAL];

__device__ __forceinline__ void bf16_split(float v, __nv_bfloat16& h, __nv_bfloat16& l) {
    h = __float2bfloat16(v);
    l = __float2bfloat16(v - __bfloat162float(h));
}

__device__ __forceinline__ void cp_async16(void* sptr, const void* gptr) {
    uint32_t sa = (uint32_t)__cvta_generic_to_shared(sptr);
    asm volatile("cp.async.cg.shared.global [%0], [%1], 16;" :: "r"(sa), "l"(gptr));
}

// ------------------------- static stream/event context ----------------------
__global__ void noop_kernel() {}

struct StreamCtx {
    cudaStream_t s1, s2;
    cudaEvent_t evStart, evPrep, evPartA, evPartB, evS1Done;
    cudaEvent_t evPool1, evPool2, evF2, evF4, evFm4, evS2Done;
    StreamCtx() {
        cudaStreamCreateWithFlags(&s1, cudaStreamNonBlocking);
        cudaStreamCreateWithFlags(&s2, cudaStreamNonBlocking);
        cudaEventCreateWithFlags(&evStart,  cudaEventDisableTiming);
        cudaEventCreateWithFlags(&evPrep,   cudaEventDisableTiming);
        cudaEventCreateWithFlags(&evPartA,  cudaEventDisableTiming);
        cudaEventCreateWithFlags(&evPartB,  cudaEventDisableTiming);
        cudaEventCreateWithFlags(&evS1Done, cudaEventDisableTiming);
        cudaEventCreateWithFlags(&evPool1,  cudaEventDisableTiming);
        cudaEventCreateWithFlags(&evPool2,  cudaEventDisableTiming);
        cudaEventCreateWithFlags(&evF2,     cudaEventDisableTiming);
        cudaEventCreateWithFlags(&evF4,     cudaEventDisableTiming);
        cudaEventCreateWithFlags(&evFm4,    cudaEventDisableTiming);
        cudaEventCreateWithFlags(&evS2Done, cudaEventDisableTiming);
        noop_kernel<<<1, 1, 0, s1>>>();
        noop_kernel<<<1, 1, 0, s2>>>();
        cudaStreamSynchronize(s1);
        cudaStreamSynchronize(s2);
    }
};
static StreamCtx g_sc;

// ------------------------- tensor-core GEMM (wmma bf16, split precision) ----
constexpr int TC_SSTRIDE = 40;
constexpr int TC_TILE    = 128 * TC_SSTRIDE;
constexpr int TC_SMEM    = 2 * 4 * TC_TILE * 2;   // 81920 B

__global__ __launch_bounds__(256, 2) void tc_gemm_kernel(
    const __nv_bfloat16* __restrict__ Ahi, const __nv_bfloat16* __restrict__ Alo, int lda,
    const __nv_bfloat16* __restrict__ Bhi, const __nv_bfloat16* __restrict__ Blo, int ldb,
    float* __restrict__ C, int N, int K)
{
    extern __shared__ char smem[];
    __nv_bfloat16* sbuf = (__nv_bfloat16*)smem;

    const int tid  = threadIdx.x;
    const int warp = tid >> 5;
    const int wm   = warp >> 1;
    const int wn   = warp & 1;
    const int m0 = blockIdx.y * 128, n0 = blockIdx.x * 128;

    wmma::fragment<wmma::accumulator, 16, 16, 16, float> acc[2][4];
#pragma unroll
    for (int i = 0; i < 2; ++i)
#pragma unroll
        for (int j = 0; j < 4; ++j)
            wmma::fill_fragment(acc[i][j], 0.0f);

    const int nch = K / 32;

    auto load_stage = [&](int stage, int k0) {
        __nv_bfloat16* st = sbuf + stage * 4 * TC_TILE;
#pragma unroll
        for (int it = 0; it < 2; ++it) {
            const int i = tid + it * 256;
            const int row = i >> 2, c = (i & 3) * 8;
            const size_t gA = (size_t)(m0 + row) * lda + k0 + c;
            const size_t gB = (size_t)(n0 + row) * ldb + k0 + c;
            const int so = row * TC_SSTRIDE + c;
            cp_async16(st + 0 * TC_TILE + so, Ahi + gA);
            cp_async16(st + 1 * TC_TILE + so, Alo + gA);
            cp_async16(st + 2 * TC_TILE + so, Bhi + gB);
            cp_async16(st + 3 * TC_TILE + so, Blo + gB);
        }
        asm volatile("cp.async.commit_group;");
    };

    load_stage(0, 0);
    for (int ch = 0; ch < nch; ++ch) {
        if (ch + 1 < nch) {
            load_stage((ch + 1) & 1, (ch + 1) * 32);
            asm volatile("cp.async.wait_group 1;");
        } else {
            asm volatile("cp.async.wait_group 0;");
        }
        __syncthreads();
        const __nv_bfloat16* st = sbuf + (ch & 1) * 4 * TC_TILE;
        const __nv_bfloat16* sAhi = st + 0 * TC_TILE;
        const __nv_bfloat16* sAlo = st + 1 * TC_TILE;
        const __nv_bfloat16* sBhi = st + 2 * TC_TILE;
        const __nv_bfloat16* sBlo = st + 3 * TC_TILE;
#pragma unroll
        for (int ks = 0; ks < 32; ks += 16) {
            wmma::fragment<wmma::matrix_a, 16, 16, 16, __nv_bfloat16, wmma::row_major> ah[2], al[2];
#pragma unroll
            for (int i = 0; i < 2; ++i) {
                wmma::load_matrix_sync(ah[i], sAhi + (wm*32 + i*16) * TC_SSTRIDE + ks, TC_SSTRIDE);
                wmma::load_matrix_sync(al[i], sAlo + (wm*32 + i*16) * TC_SSTRIDE + ks, TC_SSTRIDE);
            }
#pragma unroll
            for (int j = 0; j < 4; ++j) {
                wmma::fragment<wmma::matrix_b, 16, 16, 16, __nv_bfloat16, wmma::col_major> bh, bl;
                wmma::load_matrix_sync(bh, sBhi + (wn*64 + j*16) * TC_SSTRIDE + ks, TC_SSTRIDE);
                wmma::load_matrix_sync(bl, sBlo + (wn*64 + j*16) * TC_SSTRIDE + ks, TC_SSTRIDE);
#pragma unroll
                for (int i = 0; i < 2; ++i) {
                    wmma::mma_sync(acc[i][j], ah[i], bh, acc[i][j]);
                    wmma::mma_sync(acc[i][j], ah[i], bl, acc[i][j]);
                    wmma::mma_sync(acc[i][j], al[i], bh, acc[i][j]);
                }
            }
        }
        __syncthreads();
    }

#pragma unroll
    for (int i = 0; i < 2; ++i)
#pragma unroll
        for (int j = 0; j < 4; ++j)
            wmma::store_matrix_sync(
                C + (size_t)(m0 + wm*32 + i*16) * N + n0 + wn*64 + j*16,
                acc[i][j], N, wmma::mem_row_major);
}

// ------------------------- merged weight prep --------------------------------
__global__ void prep_weights_kernel(
    const float* __restrict__ cw1, const float* __restrict__ cw2,
    const float* __restrict__ w1, const float* __restrict__ w2,
    const float* __restrict__ w3, const float* __restrict__ w4,
    __nv_bfloat16* __restrict__ cw1hi, __nv_bfloat16* __restrict__ cw1lo,
    __nv_bfloat16* __restrict__ cw2hi, __nv_bfloat16* __restrict__ cw2lo,
    __nv_bfloat16* __restrict__ w1thi, __nv_bfloat16* __restrict__ w1tlo,
    __nv_bfloat16* __restrict__ w2thi, __nv_bfloat16* __restrict__ w2tlo,
    __nv_bfloat16* __restrict__ w3thi, __nv_bfloat16* __restrict__ w3tlo,
    __nv_bfloat16* __restrict__ w4thi, __nv_bfloat16* __restrict__ w4tlo)
{
    int i = blockIdx.x * 256 + threadIdx.x;
    const int n0 = 512*1792, n1 = 512*512, n2 = 128*256,
              n3 = 128*512,  n4 = 256*512, n5 = 256*1024;
    __nv_bfloat16 h, l;
    if (i < n0) { bf16_split(cw1[i], h, l); cw1hi[i] = h; cw1lo[i] = l; return; }
    i -= n0;
    if (i < n1) { bf16_split(cw2[i], h, l); cw2hi[i] = h; cw2lo[i] = l; return; }
    i -= n1;
    if (i < n2) {
        int k = i / 256, n = i % 256;
        bf16_split(w1[i], h, l);
        w1thi[(size_t)n * 128 + k] = h; w1tlo[(size_t)n * 128 + k] = l; return;
    }
    i -= n2;
    if (i < n3) {
        int k = i / 512, n = i % 512;
        bf16_split(w2[i], h, l);
        w2thi[(size_t)n * 128 + k] = h; w2tlo[(size_t)n * 128 + k] = l; return;
    }
    i -= n3;
    if (i < n4) {
        int k = i / 512, n = i % 512;
        bf16_split(w3[i], h, l);
        w3thi[(size_t)n * 256 + k] = h; w3tlo[(size_t)n * 256 + k] = l; return;
    }
    i -= n4;
    if (i < n5) {
        int k = i / 1024, n = i % 1024;
        bf16_split(w4[i], h, l);
        w4thi[(size_t)n * 256 + k] = h; w4tlo[(size_t)n * 256 + k] = l;
    }
}
constexpr int PREP_TOTAL = 512*1792 + 512*512 + 128*256 + 128*512 + 256*512 + 256*1024;

// ------------------------- warp-cooperative KNN-32 (single-pass float4) -----
// float4 cache {x,y,z,|p|^2}; d = |p|^2 - 2 p.q (same ordering as reference).
__device__ __forceinline__ void knn_cmpex(float& d, int& i, int lane, int s, bool up) {
    const float od = __shfl_xor_sync(0xffffffffu, d, s);
    const int   oi = __shfl_xor_sync(0xffffffffu, i, s);
    const bool lower = (lane & s) == 0;
    if ((od != d) && ((d > od) == (lower == up))) { d = od; i = oi; }
}

__global__ __launch_bounds__(512) void knn32_warp_kernel(
    const float* __restrict__ pts, int P, int* __restrict__ out)
{
    extern __shared__ float4 sp4[];
    const int b = blockIdx.y;
    const float* vb = pts + (size_t)b * P * 3;
    for (int i = threadIdx.x; i < P; i += 512) {
        const float x = vb[3*i], y = vb[3*i+1], z = vb[3*i+2];
        sp4[i] = make_float4(x, y, z, fmaf(x, x, fmaf(y, y, z * z)));
    }
    __syncthreads();
    const int lane = threadIdx.x & 31;
    const int q = blockIdx.x * 16 + (threadIdx.x >> 5);
    const float4 qp = sp4[q];
    const int qb = q & ~31;
    float Ld = 3.0e38f; int Li = 0;
    for (int j0 = 0; j0 < P; j0 += 32) {
        const float4 p = sp4[j0 + lane];
        float t = fmaf(p.x, qp.x, fmaf(p.y, qp.y, p.z * qp.z));
        float d = fmaf(-2.0f, t, p.w);
        if (j0 == qb) {                      // uniform branch; self is global min
            if (j0 + lane == q) d = 3.0e38f;
        }
        const float worst = __shfl_sync(0xffffffffu, Ld, 31);
        unsigned mask = __ballot_sync(0xffffffffu, d < worst);
        if (!mask) continue;
        if (__popc(mask) <= 8) {
            while (mask) {
                const int src = __ffs(mask) - 1;
                mask &= mask - 1;
                const float cd = __shfl_sync(0xffffffffu, d, src);
                const int   ci = j0 + src;
                const int pos = __popc(__ballot_sync(0xffffffffu, Ld < cd));
                const float pd = __shfl_up_sync(0xffffffffu, Ld, 1);
                const int   pi = __shfl_up_sync(0xffffffffu, Li, 1);
                if (lane > pos)       { Ld = pd; Li = pi; }
                else if (lane == pos) { Ld = cd; Li = ci; }
            }
        } else {
            float cd = d; int ci = j0 + lane;
#pragma unroll
            for (int k = 2; k <= 32; k <<= 1) {
                const bool up = ((lane & k) == 0);
#pragma unroll
                for (int s2 = k >> 1; s2 > 0; s2 >>= 1) knn_cmpex(cd, ci, lane, s2, up);
            }
            const float rd = __shfl_sync(0xffffffffu, cd, 31 - lane);
            const int   ri = __shfl_sync(0xffffffffu, ci, 31 - lane);
            if (rd < Ld) { Ld = rd; Li = ri; }
#pragma unroll
            for (int s2 = 16; s2 > 0; s2 >>= 1) knn_cmpex(Ld, Li, lane, s2, true);
        }
    }
    out[((size_t)b * P + q) * 32 + lane] = Li;
}

// ------------------------- nearest (argmin; float4 trick) --------------------
__global__ void nearest_kernel(const float* __restrict__ qpts, int Q,
                               const float* __restrict__ spts, int P,
                               int* __restrict__ out)
{
    extern __shared__ float4 sp4[];
    const int b = blockIdx.y;
    const float* sb = spts + (size_t)b * P * 3;
    for (int i = threadIdx.x; i < P; i += blockDim.x) {
        const float x = sb[3*i], y = sb[3*i+1], z = sb[3*i+2];
        sp4[i] = make_float4(x, y, z, fmaf(x, x, fmaf(y, y, z * z)));
    }
    __syncthreads();
    const int q = blockIdx.x * blockDim.x + threadIdx.x;
    if (q >= Q) return;
    const float* qb = qpts + ((size_t)b * Q + q) * 3;
    const float qx = qb[0], qy = qb[1], qz = qb[2];
    float best = 3.0e38f; int bi = 0;
#pragma unroll 4
    for (int j = 0; j < P; ++j) {
        const float4 p = sp4[j];
        float t = fmaf(p.x, qx, fmaf(p.y, qy, p.z * qz));
        float d = fmaf(-2.0f, t, p.w);
        if (d < best) { best = d; bi = j; }
    }
    out[(size_t)b * Q + q] = bi;
}

// ------------------------- conv_surface (vec4: 32 threads, 4 ch each) -------
__global__ void conv_surface_kernel(const float* __restrict__ verts,
                                    const int* __restrict__ nb,
                                    const float* __restrict__ dirs,
                                    __nv_bfloat16* __restrict__ ohi,
                                    __nv_bfloat16* __restrict__ olo)
{
    __shared__ float ux[32], uy[32], uz[32];
    const int bv = blockIdx.x;
    const int b = bv >> 12;
    const float* vb = verts + (size_t)b * NV * 3;
    const int v = bv & 4095;
    const int t = threadIdx.x;
    {
        const float cx = vb[3*v], cy = vb[3*v+1], cz = vb[3*v+2];
        int j = nb[(size_t)bv * 32 + t];
        float dx = vb[3*j]-cx, dy = vb[3*j+1]-cy, dz = vb[3*j+2]-cz;
        float n = fmaxf(sqrtf(dx*dx + dy*dy + dz*dz), 1e-12f);
        ux[t] = dx/n; uy[t] = dy/n; uz[t] = dz/n;
    }
    __syncthreads();
    const int c = t * 4;
    float4 D0 = *(const float4*)(dirs + c);
    float4 D1 = *(const float4*)(dirs + 128 + c);
    float4 D2 = *(const float4*)(dirs + 256 + c);
    float d0[4] = {D0.x, D0.y, D0.z, D0.w};
    float d1[4] = {D1.x, D1.y, D1.z, D1.w};
    float d2[4] = {D2.x, D2.y, D2.z, D2.w};
#pragma unroll
    for (int j = 0; j < 4; ++j) {
        float n = fmaxf(sqrtf(d0[j]*d0[j] + d1[j]*d1[j] + d2[j]*d2[j]), 1e-12f);
        d0[j] /= n; d1[j] /= n; d2[j] /= n;
    }
    float acc[4] = {0.f, 0.f, 0.f, 0.f};
#pragma unroll 4
    for (int k = 0; k < 32; ++k) {
        const float u0 = ux[k], u1 = uy[k], u2 = uz[k];
#pragma unroll
        for (int j = 0; j < 4; ++j)
            acc[j] = fmaxf(acc[j], fmaf(u0, d0[j], fmaf(u1, d1[j], u2 * d2[j])));
    }
#pragma unroll
    for (int j = 0; j < 4; ++j) {
        __nv_bfloat16 h, l; bf16_split(acc[j], h, l);
        ohi[(size_t)bv * 256 + c + j] = h;
        olo[(size_t)bv * 256 + c + j] = l;
    }
}

// ------------------------- conv_layer combine (vec4; bias folded in) --------
__global__ void conv_combine_kernel(const float* __restrict__ verts,
                                    const int* __restrict__ nb,
                                    const float* __restrict__ f,
                                    const float* __restrict__ bias,
                                    const float* __restrict__ dirs,
                                    float* __restrict__ out,
                                    __nv_bfloat16* __restrict__ ohi,
                                    __nv_bfloat16* __restrict__ olo,
                                    int ostride,
                                    int P, int C, int doRelu)
{
    __shared__ float ux[32], uy[32], uz[32];
    __shared__ int snb[32];
    const int bv = blockIdx.x;
    const int b = bv / P, v = bv % P;
    const float* vb = verts + (size_t)b * P * 3;
    const int t = threadIdx.x;
    if (t < 32) {
        const float cx = vb[3*v], cy = vb[3*v+1], cz = vb[3*v+2];
        int j = nb[(size_t)bv * 32 + t];
        snb[t] = j;
        float dx = vb[3*j]-cx, dy = vb[3*j+1]-cy, dz = vb[3*j+2]-cz;
        float n = fmaxf(sqrtf(dx*dx + dy*dy + dz*dz), 1e-12f);
        ux[t] = dx/n; uy[t] = dy/n; uz[t] = dz/n;
    }
    __syncthreads();
    const int c = t * 4;
    float4 D0 = *(const float4*)(dirs + c);
    float4 D1 = *(const float4*)(dirs + C + c);
    float4 D2 = *(const float4*)(dirs + 2*C + c);
    float d0[4] = {D0.x, D0.y, D0.z, D0.w};
    float d1[4] = {D1.x, D1.y, D1.z, D1.w};
    float d2[4] = {D2.x, D2.y, D2.z, D2.w};
#pragma unroll
    for (int j = 0; j < 4; ++j) {
        float n = fmaxf(sqrtf(d0[j]*d0[j] + d1[j]*d1[j] + d2[j]*d2[j]), 1e-12f);
        d0[j] /= n; d1[j] /= n; d2[j] /= n;
    }
    const float4 bc = *(const float4*)(bias + c);
    const float4 bs = *(const float4*)(bias + C + c);
    const float* fb   = f + (size_t)b * P * 2 * C;
    const float* fsup = fb + C + c;
    float m[4] = {-3.0e38f, -3.0e38f, -3.0e38f, -3.0e38f};
#pragma unroll 4
    for (int k = 0; k < 32; ++k) {
        const float u0 = ux[k], u1 = uy[k], u2 = uz[k];
        const float4 sup = *(const float4*)(fsup + (size_t)snb[k] * 2 * C);
        float th0 = fmaxf(0.0f, fmaf(u0, d0[0], fmaf(u1, d1[0], u2 * d2[0])));
        float th1 = fmaxf(0.0f, fmaf(u0, d0[1], fmaf(u1, d1[1], u2 * d2[1])));
        float th2 = fmaxf(0.0f, fmaf(u0, d0[2], fmaf(u1, d1[2], u2 * d2[2])));
        float th3 = fmaxf(0.0f, fmaf(u0, d0[3], fmaf(u1, d1[3], u2 * d2[3])));
        m[0] = fmaxf(m[0], th0 * (sup.x + bs.x));
        m[1] = fmaxf(m[1], th1 * (sup.y + bs.y));
        m[2] = fmaxf(m[2], th2 * (sup.z + bs.z));
        m[3] = fmaxf(m[3], th3 * (sup.w + bs.w));
    }
    const float4 ctr = *(const float4*)(fb + (size_t)v * 2 * C + c);
    float r[4] = {ctr.x + bc.x + m[0], ctr.y + bc.y + m[1],
                  ctr.z + bc.z + m[2], ctr.w + bc.w + m[3]};
    if (doRelu) {
#pragma unroll
        for (int j = 0; j < 4; ++j) r[j] = fmaxf(r[j], 0.0f);
    }
    if (out) {
        float4 o4 = {r[0], r[1], r[2], r[3]};
        *(float4*)(out + (size_t)bv * C + c) = o4;
    }
    if (ohi) {
#pragma unroll
        for (int j = 0; j < 4; ++j) {
            __nv_bfloat16 h, l; bf16_split(r[j], h, l);
            ohi[(size_t)bv * ostride + c + j] = h;
            olo[(size_t)bv * ostride + c + j] = l;
        }
    }
}

// ------------------------- pool: first-4 of sorted 32-NN --------------------
__global__ void pool_kernel(const float* __restrict__ verts,
                            const float* __restrict__ fm, int P, int C,
                            const int* __restrict__ sidx,
                            const int* __restrict__ nb32, int Q,
                            float* __restrict__ vout,
                            __nv_bfloat16* __restrict__ fhi,
                            __nv_bfloat16* __restrict__ flo)
{
    const int bq = blockIdx.x;
    const int b = bq / Q, q = bq % Q;
    const int k = threadIdx.x;
    const int qi = sidx[q];
    const int* nbq = nb32 + ((size_t)b * P + qi) * 32;
    const float* fb = fm + (size_t)b * P * C;
    float m = -3.0e38f;
#pragma unroll
    for (int s = 0; s < 4; ++s)
        m = fmaxf(m, fb[(size_t)nbq[s] * C + k]);
    __nv_bfloat16 h, l; bf16_split(m, h, l);
    fhi[(size_t)bq * C + k] = h;
    flo[(size_t)bq * C + k] = l;
    if (k < 3) {
        vout[(size_t)bq * 3 + k] = verts[((size_t)b * P + qi) * 3 + k];
    }
}

// ------------------------- global max over verts ----------------------------
__global__ void fglobal_kernel(const float* __restrict__ fm4,
                               float* __restrict__ fg)
{
    const int b = blockIdx.x, k = threadIdx.x;
    float m = -3.0e38f;
    for (int q = 0; q < NP2; ++q)
        m = fmaxf(m, fm4[((size_t)b * NP2 + q) * 512 + k]);
    fg[(size_t)b * 512 + k] = m;
}

// ------------------------- Dh1 = fg @ cw1[:,1280:1792]^T (fp32, tiny) -------
__global__ void fg_head_kernel(const float* __restrict__ fg,
                               const float* __restrict__ cw1,
                               float* __restrict__ dh1)
{
    const int warp = threadIdx.x >> 5, lane = threadIdx.x & 31;
    const int o = blockIdx.x * 8 + warp;
    const int b = blockIdx.y;
    const float* fgb = fg + (size_t)b * 512;
    const float* wr  = cw1 + (size_t)o * 1792 + 1280;
    float acc = 0.0f;
#pragma unroll
    for (int i = lane; i < 512; i += 32) acc = fmaf(fgb[i], wr[i], acc);
#pragma unroll
    for (int s = 16; s > 0; s >>= 1)
        acc += __shfl_down_sync(0xffffffffu, acc, s);
    if (lane == 0) dh1[(size_t)b * 512 + o] = acc;
}

// ------------------------- h1 combine: gather-add parts + cb1 + relu --------
__global__ void h1_combine_kernel(const float* __restrict__ Ah1,
                                  const float* __restrict__ Bh1,
                                  const float* __restrict__ Ch1,
                                  const float* __restrict__ Dh1,
                                  const float* __restrict__ cb1,
                                  const int* __restrict__ near1,
                                  const int* __restrict__ near2,
                                  __nv_bfloat16* __restrict__ h1hi,
                                  __nv_bfloat16* __restrict__ h1lo)
{
    const int bv = blockIdx.x;
    const int b = bv >> 12;
    const int n1 = near1[bv], n2 = near2[bv];
    const int o = threadIdx.x;
    float v = Ah1[(size_t)bv * 512 + o]
            + Bh1[((size_t)b * NP1 + n1) * 512 + o]
            + Ch1[((size_t)b * NP2 + n2) * 512 + o]
            + Dh1[(size_t)b * 512 + o]
            + cb1[o];
    v = fmaxf(v, 0.0f);
    __nv_bfloat16 h, l; bf16_split(v, h, l);
    h1hi[(size_t)bv * 512 + o] = h;
    h1lo[(size_t)bv * 512 + o] = l;
}

// ------------------------- final 13-way head (folds relu(h2+cb2)) -----------
__global__ void head13_kernel(const float* __restrict__ h,
                              const float* __restrict__ hbias,
                              const float* __restrict__ w,
                              const float* __restrict__ bias,
                              float* __restrict__ out)
{
    const int warp = threadIdx.x >> 5, lane = threadIdx.x & 31;
    const float* hr = h + (size_t)blockIdx.x * 512;
    const float* wr = w + (size_t)warp * 512;
    float acc = 0.0f;
#pragma unroll
    for (int i = lane; i < 512; i += 32) {
        float hv = fmaxf(hr[i] + hbias[i], 0.0f);
        acc = fmaf(hv, wr[i], acc);
    }
#pragma unroll
    for (int o = 16; o > 0; o >>= 1)
        acc += __shfl_down_sync(0xffffffffu, acc, o);
    if (lane == 0) out[(size_t)blockIdx.x * 13 + warp] = acc + bias[warp];
}

// ------------------------- launcher ------------------------------------------
extern "C" void kernel_launch(void* const* d_in, const int* in_sizes, int n_in,
                              void* d_out, int out_size)
{
    const float* verts = (const float*)d_in[0];
    const int*   sidx1 = (const int*)  d_in[1];
    const int*   sidx2 = (const int*)  d_in[2];
    const float* dir0  = (const float*)d_in[3];
    const float* w1 = (const float*)d_in[4];
    const float* b1 = (const float*)d_in[5];
    const float* d1 = (const float*)d_in[6];
    const float* w2 = (const float*)d_in[7];
    const float* b2 = (const float*)d_in[8];
    const float* d2 = (const float*)d_in[9];
    const float* w3 = (const float*)d_in[10];
    const float* b3 = (const float*)d_in[11];
    const float* d3 = (const float*)d_in[12];
    const float* w4 = (const float*)d_in[13];
    const float* b4 = (const float*)d_in[14];
    const float* d4 = (const float*)d_in[15];
    const float* cw1 = (const float*)d_in[16];
    const float* cb1 = (const float*)d_in[17];
    const float* cw2 = (const float*)d_in[18];
    const float* cb2 = (const float*)d_in[19];
    const float* cw3 = (const float*)d_in[20];
    const float* cb3 = (const float*)d_in[21];

    void* sp = nullptr;
    cudaGetSymbolAddress(&sp, g_scratch);
    char* s = (char*)sp;
    float* f1   = (float*)(s + SC_F1);
    float* fm1  = (float*)(s + SC_FM1);
    float* vp1  = (float*)(s + SC_VP1);
    float* f2   = (float*)(s + SC_F2);
    float* f3   = (float*)(s + SC_F3);
    float* fm3  = (float*)(s + SC_FM3);
    float* vp2  = (float*)(s + SC_VP2);
    float* f4   = (float*)(s + SC_F4);
    float* fm4  = (float*)(s + SC_FM4);
    float* fg   = (float*)(s + SC_FG);
    __nv_bfloat16* pahi = (__nv_bfloat16*)(s + SC_PAHI);
    __nv_bfloat16* palo = (__nv_bfloat16*)(s + SC_PALO);
    __nv_bfloat16* pbhi = (__nv_bfloat16*)(s + SC_PBHI);
    __nv_bfloat16* pblo = (__nv_bfloat16*)(s + SC_PBLO);
    __nv_bfloat16* pchi = (__nv_bfloat16*)(s + SC_PCHI);
    __nv_bfloat16* pclo = (__nv_bfloat16*)(s + SC_PCLO);
    float* Ah1 = (float*)(s + SC_AH1);
    float* Bh1 = (float*)(s + SC_BH1);
    float* Ch1 = (float*)(s + SC_CH1);
    float* Dh1 = (float*)(s + SC_DH1);
    __nv_bfloat16* h1hi = (__nv_bfloat16*)(s + SC_H1HI);
    __nv_bfloat16* h1lo = (__nv_bfloat16*)(s + SC_H1LO);
    float* h2   = (float*)(s + SC_H2);
    __nv_bfloat16* cw1hi = (__nv_bfloat16*)(s + SC_CW1HI);
    __nv_bfloat16* cw1lo = (__nv_bfloat16*)(s + SC_CW1LO);
    __nv_bfloat16* cw2hi = (__nv_bfloat16*)(s + SC_CW2HI);
    __nv_bfloat16* cw2lo = (__nv_bfloat16*)(s + SC_CW2LO);
    __nv_bfloat16* fmp1hi = (__nv_bfloat16*)(s + SC_FMP1HI);
    __nv_bfloat16* fmp1lo = (__nv_bfloat16*)(s + SC_FMP1LO);
    __nv_bfloat16* fmp2hi = (__nv_bfloat16*)(s + SC_FMP2HI);
    __nv_bfloat16* fmp2lo = (__nv_bfloat16*)(s + SC_FMP2LO);
    __nv_bfloat16* w1thi = (__nv_bfloat16*)(s + SC_W1THI);
    __nv_bfloat16* w1tlo = (__nv_bfloat16*)(s + SC_W1TLO);
    __nv_bfloat16* w2thi = (__nv_bfloat16*)(s + SC_W2THI);
    __nv_bfloat16* w2tlo = (__nv_bfloat16*)(s + SC_W2TLO);
    __nv_bfloat16* w3thi = (__nv_bfloat16*)(s + SC_W3THI);
    __nv_bfloat16* w3tlo = (__nv_bfloat16*)(s + SC_W3TLO);
    __nv_bfloat16* w4thi = (__nv_bfloat16*)(s + SC_W4THI);
    __nv_bfloat16* w4tlo = (__nv_bfloat16*)(s + SC_W4TLO);
    int* nb1   = (int*)(s + SC_NB1);
    int* nb2   = (int*)(s + SC_NB2);
    int* nb3   = (int*)(s + SC_NB3);
    int* near1 = (int*)(s + SC_NEAR1);
    int* near2 = (int*)(s + SC_NEAR2);

    cudaFuncSetAttribute(tc_gemm_kernel,
                         cudaFuncAttributeMaxDynamicSharedMemorySize, TC_SMEM);
    cudaFuncSetAttribute(knn32_warp_kernel,
                         cudaFuncAttributeMaxDynamicSharedMemorySize, NV * 16);
    cudaFuncSetAttribute(nearest_kernel,
                         cudaFuncAttributeMaxDynamicSharedMemorySize, NP1 * 16);

    // ---- fork: weight prep on s2 overlaps knn1 on main -------------------
    cudaEventRecord(g_sc.evStart, 0);
    cudaStreamWaitEvent(g_sc.s2, g_sc.evStart, 0);
    prep_weights_kernel<<<(PREP_TOTAL + 255)/256, 256, 0, g_sc.s2>>>(
        cw1, cw2, w1, w2, w3, w4,
        cw1hi, cw1lo, cw2hi, cw2lo,
        w1thi, w1tlo, w2thi, w2tlo, w3thi, w3tlo, w4thi, w4tlo);
    cudaEventRecord(g_sc.evPrep, g_sc.s2);

    // Level 0/1 on full 4096-point cloud (main). Single-pass KNN (R15).
    knn32_warp_kernel<<<dim3(NV/16, BS), 512, NV * 16>>>(verts, NV, nb1);
    conv_surface_kernel<<<BS*NV, 32>>>(verts, nb1, dir0, pahi, palo);
    cudaStreamWaitEvent(0, g_sc.evPrep, 0);
    tc_gemm_kernel<<<dim3(2, 128), 256, TC_SMEM>>>(
        pahi, palo, 256, w1thi, w1tlo, 128, f1, 256, 128);
    conv_combine_kernel<<<BS*NV, 32>>>(verts, nb1, f1, b1, d1, fm1,
        pahi + 128, palo + 128, 256, NV, 128, 1);
    cudaEventRecord(g_sc.evPartA, 0);

    // ---- fork: Ah1 on s1 overlaps the level-2/3 chain --------------------
    cudaStreamWaitEvent(g_sc.s1, g_sc.evPartA, 0);
    tc_gemm_kernel<<<dim3(4, 128), 256, TC_SMEM, g_sc.s1>>>(
        pahi, palo, 256, cw1hi, cw1lo, 1792, Ah1, 512, 256);

    // Pool 1 (main); nearest1 + f2 on s2 overlap knn2 on main
    pool_kernel<<<BS*NP1, 128>>>(verts, fm1, NV, 128, sidx1, nb1, NP1, vp1, fmp1hi, fmp1lo);
    cudaEventRecord(g_sc.evPool1, 0);
    cudaStreamWaitEvent(g_sc.s2, g_sc.evPool1, 0);
    nearest_kernel<<<dim3(NV/256, BS), 256, NP1 * 16, g_sc.s2>>>(
        verts, NV, vp1, NP1, near1);
    tc_gemm_kernel<<<dim3(4, 32), 256, TC_SMEM, g_sc.s2>>>(
        fmp1hi, fmp1lo, 128, w2thi, w2tlo, 128, f2, 512, 128);
    cudaEventRecord(g_sc.evF2, g_sc.s2);

    knn32_warp_kernel<<<dim3(NP1/16, BS), 512, NP1 * 16>>>(vp1, NP1, nb2);

    cudaStreamWaitEvent(0, g_sc.evF2, 0);
    conv_combine_kernel<<<BS*NP1, 64>>>(vp1, nb2, f2, b2, d2, nullptr,
        pbhi, pblo, 512, NP1, 256, 1);
    tc_gemm_kernel<<<dim3(4, 32), 256, TC_SMEM>>>(
        pbhi, pblo, 512, w3thi, w3tlo, 256, f3, 512, 256);
    conv_combine_kernel<<<BS*NP1, 64>>>(vp1, nb2, f3, b3, d3, fm3,
        pbhi + 256, pblo + 256, 512, NP1, 256, 1);
    cudaEventRecord(g_sc.evPartB, 0);

    // ---- s1: Bh1 after partB, overlaps the level-4 chain -----------------
    cudaStreamWaitEvent(g_sc.s1, g_sc.evPartB, 0);
    tc_gemm_kernel<<<dim3(4, 32), 256, TC_SMEM, g_sc.s1>>>(
        pbhi, pblo, 512, cw1hi + 256, cw1lo + 256, 1792, Bh1, 512, 512);
    cudaEventRecord(g_sc.evS1Done, g_sc.s1);

    // Pool 2 (main); nearest2 + f4 on s2 overlap knn3 on main
    pool_kernel<<<BS*NP2, 256>>>(vp1, fm3, NP1, 256, sidx2, nb2, NP2, vp2, fmp2hi, fmp2lo);
    cudaEventRecord(g_sc.evPool2, 0);
    cudaStreamWaitEvent(g_sc.s2, g_sc.evPool2, 0);
    nearest_kernel<<<dim3(NV/256, BS), 256, NP2 * 16, g_sc.s2>>>(
        verts, NV, vp2, NP2, near2);
    tc_gemm_kernel<<<dim3(8, 8), 256, TC_SMEM, g_sc.s2>>>(
        fmp2hi, fmp2lo, 256, w4thi, w4tlo, 256, f4, 1024, 256);
    cudaEventRecord(g_sc.evF4, g_sc.s2);

    knn32_warp_kernel<<<dim3(NP2/16, BS), 512, NP2 * 16>>>(vp2, NP2, nb3);

    cudaStreamWaitEvent(0, g_sc.evF4, 0);
    conv_combine_kernel<<<BS*NP2, 128>>>(vp2, nb3, f4, b4, d4, fm4,
        pchi, pclo, 512, NP2, 512, 0);
    cudaEventRecord(g_sc.evFm4, 0);

    // fglobal + fg_head on s2 overlap Ch1 GEMM on main
    cudaStreamWaitEvent(g_sc.s2, g_sc.evFm4, 0);
    fglobal_kernel<<<BS, 512, 0, g_sc.s2>>>(fm4, fg);
    fg_head_kernel<<<dim3(64, BS), 256, 0, g_sc.s2>>>(fg, cw1, Dh1);
    cudaEventRecord(g_sc.evS2Done, g_sc.s2);

    tc_gemm_kernel<<<dim3(4, 8), 256, TC_SMEM>>>(
        pchi, pclo, 512, cw1hi + 768, cw1lo + 768, 1792, Ch1, 512, 512);

    // ---- join all, then combine + h2 + head ------------------------------
    cudaStreamWaitEvent(0, g_sc.evS1Done, 0);
    cudaStreamWaitEvent(0, g_sc.evS2Done, 0);
    h1_combine_kernel<<<BS*NV, 512>>>(Ah1, Bh1, Ch1, Dh1, cb1, near1, near2, h1hi, h1lo);
    tc_gemm_kernel<<<dim3(512/128, (BS*NV)/128), 256, TC_SMEM>>>(
        h1hi, h1lo, 512, cw2hi, cw2lo, 512, h2, 512, 512);
    head13_kernel<<<BS*NV, 13*32>>>(h2, cb2, cw3, cb3, (float*)d_out);
}